// round 11
// baseline (speedup 1.0000x reference)
#include <cuda_runtime.h>

// VPNNetwork (R11 = R10 rerun): constant-memory Phi weights (pre-transposed,
// f32-pair packed), 1-sample-per-thread GEMM (phi stays in registers, no
// handoff), register VI, obs-logits from live smem, v-logits from registers.
//   d_in[0] obs_flat [B,48] | d_in[1] Phi_w [48,48] | d_in[2] Phi_b [48]
//   d_in[3] Logit_w [4,36]  | d_in[4] Logit_b [4]   | out [B,4] f32

#define BT 128
#define ST 132

typedef unsigned long long ull;
__device__ __forceinline__ ull pk(float a, float b) {
    ull d; asm("mov.b64 %0, {%1, %2};" : "=l"(d) : "f"(a), "f"(b)); return d;
}
__device__ __forceinline__ ull dup2(float x) {
    ull d; asm("mov.b64 %0, {%1, %1};" : "=l"(d) : "f"(x)); return d;
}
__device__ __forceinline__ void upk(ull d, float& a, float& b) {
    asm("mov.b64 {%0, %1}, %2;" : "=f"(a), "=f"(b) : "l"(d));
}
__device__ __forceinline__ ull fma2(ull a, ull b, ull c) {
    ull d; asm("fma.rn.f32x2 %0, %1, %2, %3;" : "=l"(d) : "l"(a), "l"(b), "l"(c));
    return d;
}
__device__ __forceinline__ ull add2(ull a, ull b) {
    ull d; asm("add.rn.f32x2 %0, %1, %2;" : "=l"(d) : "l"(a), "l"(b)); return d;
}

// cW[i*24 + t] = ( Pw[(2t)*48 + i], Pw[(2t+1)*48 + i] )  -- transposed pairs
__constant__ ull   cW[48 * 24];
__constant__ float cPb[48];
__device__   ull   g_cw[48 * 24];     // staging buffer for the D2D symbol copy

__global__ void transpose_k(const float* __restrict__ Pw) {
    int idx = blockIdx.x * blockDim.x + threadIdx.x;   // 0..1151
    if (idx < 48 * 24) {
        int i = idx / 24, t = idx - i * 24;
        g_cw[idx] = pk(Pw[(2 * t) * 48 + i], Pw[(2 * t + 1) * 48 + i]);
    }
}

__global__ __launch_bounds__(BT, 4) void vpn_kernel(
    const float* __restrict__ obs, const float* __restrict__ Pw,
    const float* __restrict__ Lw,  const float* __restrict__ Lb,
    float* __restrict__ out)
{
    __shared__ __align__(16) float xs[32 * ST];  // dense obs rows [2c+(ch>>1)][s]
    __shared__ __align__(16) float wt[48 * 48];  // wt[i*48+o] (for one-hot add only)
    __shared__ __align__(16) float lw[144];      // lw[k*4+a] = Lw[a*36+k]
    __shared__ __align__(16) float lb[4];
    __shared__ __align__(16) int spos[BT];

    const int tid = threadIdx.x;
    const int base = blockIdx.x * BT;

    for (int idx = tid; idx < 48 * 48; idx += BT) {
        int o = idx / 48, i = idx - o * 48;
        wt[i * 48 + o] = Pw[idx];
    }
    for (int idx = tid; idx < 144; idx += BT) {
        int a = idx / 36, k = idx - a * 36;
        lw[k * 4 + a] = Lw[idx];
    }
    if (tid < 4) lb[tid] = Lb[tid];

    // ---- stage dense obs rows; agent pos detected inline ----
    const float4* g4 = reinterpret_cast<const float4*>(obs + (size_t)base * 48);
    #pragma unroll
    for (int k = 0; k < 12; k++) {
        int idx4 = tid + k * BT;
        float4 q = g4[idx4];
        int s = idx4 / 12, e0 = (idx4 - s * 12) * 4;
        float vv[4] = {q.x, q.y, q.z, q.w};
        #pragma unroll
        for (int j = 0; j < 4; j++) {
            int e = e0 + j, c = e / 3, ch = e - c * 3;
            if (ch == 1) { if (vv[j] != 0.0f) spos[s] = c; }
            else xs[(2 * c + (ch >> 1)) * ST + s] = vv[j];
        }
    }
    __syncthreads();

    // ---- Phi GEMM: 1 sample (=tid) x 48 outputs, weights from constant ----
    ull acc[24];
    {
        const ull* pb2 = reinterpret_cast<const ull*>(cPb);
        #pragma unroll
        for (int t = 0; t < 24; t++) acc[t] = pb2[t];
    }
    #pragma unroll
    for (int r = 0; r < 32; r++) {
        const int e = 3 * (r >> 1) + ((r & 1) << 1);   // input index, ch in {0,2}
        float x = xs[r * ST + tid];
        ull xx = dup2(x);
        #pragma unroll
        for (int t = 0; t < 24; t++)
            acc[t] = fma2(xx, cW[e * 24 + t], acc[t]);  // uniform const load
    }
    // one-hot ch1: += wt row (3*pos+1) (value exactly 1.0)
    const int mypos = spos[tid];
    {
        const ull* hr = reinterpret_cast<const ull*>(&wt[(3 * mypos + 1) * 48]);
        #pragma unroll
        for (int t = 0; t < 24; t++) acc[t] = add2(acc[t], hr[t]);
    }
    float ph[48];
    #pragma unroll
    for (int t = 0; t < 24; t++) upk(acc[t], ph[2 * t], ph[2 * t + 1]);

    // ---- obs part of logits (xs rows live; never overwritten) ----
    const int phh = mypos >> 2, pww = mypos & 3;
    float4 w17 = *reinterpret_cast<const float4*>(lw + 17 * 4); // center ch1, val 1.0
    float lg0 = lb[0] + w17.x, lg1 = lb[1] + w17.y;
    float lg2 = lb[2] + w17.z, lg3 = lb[3] + w17.w;
    #pragma unroll
    for (int h = 0; h < 4; h++)
        #pragma unroll
        for (int w = 0; w < 4; w++) {
            const int c = h * 4 + w;
            int di = h - phh + 1, dj = w - pww + 1;
            if ((unsigned)di < 3u && (unsigned)dj < 3u) {
                int kb = (di * 3 + dj) * 4;
                float o0 = xs[(2 * c + 0) * ST + tid];
                float o2 = xs[(2 * c + 1) * ST + tid];
                float4 a0 = *reinterpret_cast<const float4*>(lw + (kb + 0) * 4);
                float4 a2 = *reinterpret_cast<const float4*>(lw + (kb + 2) * 4);
                lg0 = fmaf(o0, a0.x, lg0); lg1 = fmaf(o0, a0.y, lg1);
                lg2 = fmaf(o0, a0.z, lg2); lg3 = fmaf(o0, a0.w, lg3);
                lg0 = fmaf(o2, a2.x, lg0); lg1 = fmaf(o2, a2.y, lg1);
                lg2 = fmaf(o2, a2.z, lg2); lg3 = fmaf(o2, a2.w, lg3);
            }
        }

    // ---- VI (phi already in registers) ----
    float rin[16], rout[16], p_[16], v_[16];
    #pragma unroll
    for (int c = 0; c < 16; c++) {
        rin[c]  = ph[3 * c + 0];
        rout[c] = ph[3 * c + 1];
        p_[c]   = ph[3 * c + 2];
        v_[c]   = 0.0f;
    }
    float rrU[16], rrD[16], rrL[16], rrR[16];
    #pragma unroll
    for (int h = 0; h < 4; h++)
        #pragma unroll
        for (int w = 0; w < 4; w++) {
            int c = h * 4 + w; float ro = rout[c];
            if (h > 0) rrU[c] = (rin[c - 4] != 0.0f) ? rin[c - 4] - ro : 0.0f;
            if (h < 3) rrD[c] = (rin[c + 4] != 0.0f) ? rin[c + 4] - ro : 0.0f;
            if (w > 0) rrL[c] = (rin[c - 1] != 0.0f) ? rin[c - 1] - ro : 0.0f;
            if (w < 3) rrR[c] = (rin[c + 1] != 0.0f) ? rin[c + 1] - ro : 0.0f;
        }
    #pragma unroll 4
    for (int k = 0; k < 20; k++) {
        float nv[16];
        #pragma unroll
        for (int h = 0; h < 4; h++)
            #pragma unroll
            for (int w = 0; w < 4; w++) {
                int c = h * 4 + w; float best = v_[c];
                if (h > 0) best = fmaxf(best, fmaf(p_[c], v_[c - 4], rrU[c]));
                if (h < 3) best = fmaxf(best, fmaf(p_[c], v_[c + 4], rrD[c]));
                if (w > 0) best = fmaxf(best, fmaf(p_[c], v_[c - 1], rrL[c]));
                if (w < 3) best = fmaxf(best, fmaf(p_[c], v_[c + 1], rrR[c]));
                nv[c] = best;
            }
        #pragma unroll
        for (int c = 0; c < 16; c++) v_[c] = nv[c];
    }

    // ---- v part of logits (values in registers) ----
    #pragma unroll
    for (int h = 0; h < 4; h++)
        #pragma unroll
        for (int w = 0; w < 4; w++) {
            const int c = h * 4 + w;
            int di = h - phh + 1, dj = w - pww + 1;
            if ((unsigned)di < 3u && (unsigned)dj < 3u) {
                int kb = (di * 3 + dj) * 4;
                float4 a3 = *reinterpret_cast<const float4*>(lw + (kb + 3) * 4);
                float vv = v_[c];
                lg0 = fmaf(vv, a3.x, lg0); lg1 = fmaf(vv, a3.y, lg1);
                lg2 = fmaf(vv, a3.z, lg2); lg3 = fmaf(vv, a3.w, lg3);
            }
        }

    reinterpret_cast<float4*>(out)[base + tid] = make_float4(lg0, lg1, lg2, lg3);
}

extern "C" void kernel_launch(void* const* d_in, const int* in_sizes, int n_in,
                              void* d_out, int out_size)
{
    const float* obs = (const float*)d_in[0];
    const float* Pw  = (const float*)d_in[1];
    const float* Pb  = (const float*)d_in[2];
    const float* Lw  = (const float*)d_in[3];
    const float* Lb  = (const float*)d_in[4];
    float* out = (float*)d_out;
    int B = in_sizes[0] / 48;                 // 262144

    // transpose weights into pairs, then D2D async copies into constant memory
    transpose_k<<<(48 * 24 + 127) / 128, 128>>>(Pw);
    void* symaddr = nullptr;
    cudaGetSymbolAddress(&symaddr, g_cw);
    cudaMemcpyToSymbolAsync(cW, symaddr, sizeof(cW), 0, cudaMemcpyDeviceToDevice);
    cudaMemcpyToSymbolAsync(cPb, Pb, 48 * sizeof(float), 0, cudaMemcpyDeviceToDevice);

    vpn_kernel<<<B / BT, BT>>>(obs, Pw, Lw, Lb, out);
}

// round 12
// speedup vs baseline: 1.1269x; 1.1269x over previous
#include <cuda_runtime.h>

// VPNNetwork fused (R12): R9 + sample-major phi handoff (vectorized LDS).
//   d_in[0] obs_flat [B,48] | d_in[1] Phi_w [48,48] | d_in[2] Phi_b [48]
//   d_in[3] Logit_w [4,36]  | d_in[4] Logit_b [4]   | out [B,4] f32

#define BT 128
#define ST 132          // element-major obs stride (floats)
#define PS 52           // sample-major phi row stride (floats, 16B-multiple)

typedef unsigned long long ull;
__device__ __forceinline__ ull dup2(float x) {
    ull d; asm("mov.b64 %0, {%1, %1};" : "=l"(d) : "f"(x)); return d;
}
__device__ __forceinline__ void upk(ull d, float& a, float& b) {
    asm("mov.b64 {%0, %1}, %2;" : "=f"(a), "=f"(b) : "l"(d));
}
__device__ __forceinline__ ull fma2(ull a, ull b, ull c) {
    ull d; asm("fma.rn.f32x2 %0, %1, %2, %3;" : "=l"(d) : "l"(a), "l"(b), "l"(c));
    return d;
}
__device__ __forceinline__ ull add2(ull a, ull b) {
    ull d; asm("add.rn.f32x2 %0, %1, %2;" : "=l"(d) : "l"(a), "l"(b)); return d;
}

__global__ __launch_bounds__(BT, 5) void vpn_kernel(
    const float* __restrict__ obs, const float* __restrict__ Pw,
    const float* __restrict__ Pb,  const float* __restrict__ Lw,
    const float* __restrict__ Lb,  float* __restrict__ out)
{
    // unified region: phase 1 = obs element-major [e<32][ST]; phase 2 = phi
    // sample-major [s<128][PS]. 128*52 = 6656 floats covers both views.
    __shared__ __align__(16) float ar[128 * PS];
    __shared__ __align__(16) float wt[48 * 48]; // wt[i*48+o] = Pw[o*48+i]
    __shared__ __align__(16) float pb[48];
    __shared__ __align__(16) float lw[144];     // lw[k*4+a] = Lw[a*36+k]
    __shared__ __align__(16) float lb[4];
    __shared__ __align__(16) int spos[BT];

    const int tid = threadIdx.x;
    const int base = blockIdx.x * BT;

    for (int idx = tid; idx < 48 * 48; idx += BT) {
        int o = idx / 48, i = idx - o * 48;
        wt[i * 48 + o] = Pw[idx];
    }
    if (tid < 48) pb[tid] = Pb[tid];
    for (int idx = tid; idx < 144; idx += BT) {
        int a = idx / 36, k = idx - a * 36;
        lw[k * 4 + a] = Lw[idx];
    }
    if (tid < 4) lb[tid] = Lb[tid];

    // ---- stage dense obs rows ar[(2c+(ch>>1))*ST + s]; pos detected inline ----
    const float4* g4 = reinterpret_cast<const float4*>(obs + (size_t)base * 48);
    #pragma unroll
    for (int k = 0; k < 12; k++) {
        int idx4 = tid + k * BT;
        float4 q = g4[idx4];
        int s = idx4 / 12, e0 = (idx4 - s * 12) * 4;
        float vv[4] = {q.x, q.y, q.z, q.w};
        #pragma unroll
        for (int j = 0; j < 4; j++) {
            int e = e0 + j, c = e / 3, ch = e - c * 3;
            if (ch == 1) { if (vv[j] != 0.0f) spos[s] = c; }
            else ar[(2 * c + (ch >> 1)) * ST + s] = vv[j];
        }
    }
    __syncthreads();

    // ---- Phi GEMM: 4 samples x 12 outputs/thread, f32x2 output-packed ----
    const int mg = tid >> 2, ng = tid & 3, ob = ng * 12;
    ull acc[4][6];
    {
        const ull* pb2 = reinterpret_cast<const ull*>(pb + ob);
        #pragma unroll
        for (int t = 0; t < 6; t++) {
            ull b = pb2[t];
            acc[0][t] = b; acc[1][t] = b; acc[2][t] = b; acc[3][t] = b;
        }
    }
    #pragma unroll
    for (int r = 0; r < 32; r++) {
        const int e = 3 * (r >> 1) + ((r & 1) << 1);    // input index, ch in {0,2}
        float4 xv = *reinterpret_cast<const float4*>(&ar[r * ST + 4 * mg]);
        const ulonglong2* wr = reinterpret_cast<const ulonglong2*>(&wt[e * 48 + ob]);
        ulonglong2 wa = wr[0], wb = wr[1], wc = wr[2];
        ull x[4] = {dup2(xv.x), dup2(xv.y), dup2(xv.z), dup2(xv.w)};
        #pragma unroll
        for (int j = 0; j < 4; j++) {
            acc[j][0] = fma2(x[j], wa.x, acc[j][0]);
            acc[j][1] = fma2(x[j], wa.y, acc[j][1]);
            acc[j][2] = fma2(x[j], wb.x, acc[j][2]);
            acc[j][3] = fma2(x[j], wb.y, acc[j][3]);
            acc[j][4] = fma2(x[j], wc.x, acc[j][4]);
            acc[j][5] = fma2(x[j], wc.y, acc[j][5]);
        }
    }
    // one-hot ch1: += wt row (3*pos+1) (value exactly 1.0)
    {
        int4 p4 = reinterpret_cast<const int4*>(spos)[mg];
        int pj[4] = {p4.x, p4.y, p4.z, p4.w};
        #pragma unroll
        for (int j = 0; j < 4; j++) {
            const ulonglong2* hr = reinterpret_cast<const ulonglong2*>(
                &wt[(3 * pj[j] + 1) * 48 + ob]);
            ulonglong2 ha = hr[0], hb = hr[1], hc = hr[2];
            acc[j][0] = add2(acc[j][0], ha.x); acc[j][1] = add2(acc[j][1], ha.y);
            acc[j][2] = add2(acc[j][2], hb.x); acc[j][3] = add2(acc[j][3], hb.y);
            acc[j][4] = add2(acc[j][4], hc.x); acc[j][5] = add2(acc[j][5], hc.y);
        }
    }
    float ph[4][12];
    #pragma unroll
    for (int j = 0; j < 4; j++)
        #pragma unroll
        for (int t = 0; t < 6; t++) upk(acc[j][t], ph[j][2 * t], ph[j][2 * t + 1]);

    // ---- obs part of logits (obs rows still alive; 1 thread = sample tid) ----
    const int mypos = spos[tid];
    const int phh = mypos >> 2, pww = mypos & 3;
    float4 w17 = *reinterpret_cast<const float4*>(lw + 17 * 4); // center ch1, val 1.0
    float lg0 = lb[0] + w17.x, lg1 = lb[1] + w17.y;
    float lg2 = lb[2] + w17.z, lg3 = lb[3] + w17.w;
    #pragma unroll
    for (int h = 0; h < 4; h++)
        #pragma unroll
        for (int w = 0; w < 4; w++) {
            const int c = h * 4 + w;
            int di = h - phh + 1, dj = w - pww + 1;
            if ((unsigned)di < 3u && (unsigned)dj < 3u) {
                int kb = (di * 3 + dj) * 4;
                float o0 = ar[(2 * c + 0) * ST + tid];
                float o2 = ar[(2 * c + 1) * ST + tid];
                float4 a0 = *reinterpret_cast<const float4*>(lw + (kb + 0) * 4);
                float4 a2 = *reinterpret_cast<const float4*>(lw + (kb + 2) * 4);
                lg0 = fmaf(o0, a0.x, lg0); lg1 = fmaf(o0, a0.y, lg1);
                lg2 = fmaf(o0, a0.z, lg2); lg3 = fmaf(o0, a0.w, lg3);
                lg0 = fmaf(o2, a2.x, lg0); lg1 = fmaf(o2, a2.y, lg1);
                lg2 = fmaf(o2, a2.z, lg2); lg3 = fmaf(o2, a2.w, lg3);
            }
        }

    // ---- overwrite ar with phi, SAMPLE-major: ar[s*PS + o] ----
    __syncthreads();
    #pragma unroll
    for (int j = 0; j < 4; j++) {
        float* row = ar + (4 * mg + j) * PS + ob;
        *reinterpret_cast<float4*>(row + 0) =
            make_float4(ph[j][0], ph[j][1], ph[j][2], ph[j][3]);
        *reinterpret_cast<float4*>(row + 4) =
            make_float4(ph[j][4], ph[j][5], ph[j][6], ph[j][7]);
        *reinterpret_cast<float4*>(row + 8) =
            make_float4(ph[j][8], ph[j][9], ph[j][10], ph[j][11]);
    }
    __syncthreads();

    // ---- VI: read own phi row with 12 LDS.128 ----
    float phr[48];
    {
        const float4* row4 = reinterpret_cast<const float4*>(ar + tid * PS);
        #pragma unroll
        for (int u = 0; u < 12; u++) {
            float4 q = row4[u];
            phr[4 * u + 0] = q.x; phr[4 * u + 1] = q.y;
            phr[4 * u + 2] = q.z; phr[4 * u + 3] = q.w;
        }
    }
    float rin[16], rout[16], p_[16], v_[16];
    #pragma unroll
    for (int c = 0; c < 16; c++) {
        rin[c]  = phr[3 * c + 0];
        rout[c] = phr[3 * c + 1];
        p_[c]   = phr[3 * c + 2];
        v_[c]   = 0.0f;
    }
    float rrU[16], rrD[16], rrL[16], rrR[16];
    #pragma unroll
    for (int h = 0; h < 4; h++)
        #pragma unroll
        for (int w = 0; w < 4; w++) {
            int c = h * 4 + w; float ro = rout[c];
            if (h > 0) rrU[c] = (rin[c - 4] != 0.0f) ? rin[c - 4] - ro : 0.0f;
            if (h < 3) rrD[c] = (rin[c + 4] != 0.0f) ? rin[c + 4] - ro : 0.0f;
            if (w > 0) rrL[c] = (rin[c - 1] != 0.0f) ? rin[c - 1] - ro : 0.0f;
            if (w < 3) rrR[c] = (rin[c + 1] != 0.0f) ? rin[c + 1] - ro : 0.0f;
        }
    #pragma unroll 4
    for (int k = 0; k < 20; k++) {
        float nv[16];
        #pragma unroll
        for (int h = 0; h < 4; h++)
            #pragma unroll
            for (int w = 0; w < 4; w++) {
                int c = h * 4 + w; float best = v_[c];
                if (h > 0) best = fmaxf(best, fmaf(p_[c], v_[c - 4], rrU[c]));
                if (h < 3) best = fmaxf(best, fmaf(p_[c], v_[c + 4], rrD[c]));
                if (w > 0) best = fmaxf(best, fmaf(p_[c], v_[c - 1], rrL[c]));
                if (w < 3) best = fmaxf(best, fmaf(p_[c], v_[c + 1], rrR[c]));
                nv[c] = best;
            }
        #pragma unroll
        for (int c = 0; c < 16; c++) v_[c] = nv[c];
    }

    // ---- v part of logits (values in registers) ----
    #pragma unroll
    for (int h = 0; h < 4; h++)
        #pragma unroll
        for (int w = 0; w < 4; w++) {
            const int c = h * 4 + w;
            int di = h - phh + 1, dj = w - pww + 1;
            if ((unsigned)di < 3u && (unsigned)dj < 3u) {
                int kb = (di * 3 + dj) * 4;
                float4 a3 = *reinterpret_cast<const float4*>(lw + (kb + 3) * 4);
                float vv = v_[c];
                lg0 = fmaf(vv, a3.x, lg0); lg1 = fmaf(vv, a3.y, lg1);
                lg2 = fmaf(vv, a3.z, lg2); lg3 = fmaf(vv, a3.w, lg3);
            }
        }

    reinterpret_cast<float4*>(out)[base + tid] = make_float4(lg0, lg1, lg2, lg3);
}

extern "C" void kernel_launch(void* const* d_in, const int* in_sizes, int n_in,
                              void* d_out, int out_size)
{
    const float* obs = (const float*)d_in[0];
    const float* Pw  = (const float*)d_in[1];
    const float* Pb  = (const float*)d_in[2];
    const float* Lw  = (const float*)d_in[3];
    const float* Lb  = (const float*)d_in[4];
    float* out = (float*)d_out;
    int B = in_sizes[0] / 48;                 // 262144
    vpn_kernel<<<B / BT, BT>>>(obs, Pw, Pb, Lw, Lb, out);
}